// round 7
// baseline (speedup 1.0000x reference)
#include <cuda_runtime.h>

// FeedForwardQuantum: out = relu(cos(x+theta) @ W1 + b1) @ W2 + b2
// ntok = B*S = 524288, E = 8, F = 32.
// R7: R6 math (e-/f-packed f32x2, no weight duplication) with 1 token/thread
// and 256-thread blocks to cut the live register set (~104 -> ~75) and raise
// occupancy toward the ~10us packed-fma pipe floor (FFMA2 rt_SMSP=2).

using ull = unsigned long long;

static constexpr int E = 8;
static constexpr int F = 32;

// ---- packed f32x2 helpers ------------------------------------------------
__device__ __forceinline__ ull pk2(float lo, float hi) {
    ull r; asm("mov.b64 %0, {%1,%2};" : "=l"(r) : "f"(lo), "f"(hi)); return r;
}
__device__ __forceinline__ void up2(ull v, float& lo, float& hi) {
    asm("mov.b64 {%0,%1}, %2;" : "=f"(lo), "=f"(hi) : "l"(v));
}
__device__ __forceinline__ ull dup2(float f) {
    ull r; asm("mov.b64 %0, {%1,%1};" : "=l"(r) : "f"(f)); return r;
}
__device__ __forceinline__ ull fma2(ull a, ull b, ull c) {
    ull r; asm("fma.rn.f32x2 %0, %1, %2, %3;" : "=l"(r) : "l"(a), "l"(b), "l"(c)); return r;
}
__device__ __forceinline__ ull add2(ull a, ull b) {
    ull r; asm("add.rn.f32x2 %0, %1, %2;" : "=l"(r) : "l"(a), "l"(b)); return r;
}
__device__ __forceinline__ ull mul2(ull a, ull b) {
    ull r; asm("mul.rn.f32x2 %0, %1, %2;" : "=l"(r) : "l"(a), "l"(b)); return r;
}

// ---- packed cosine: 2pi Cody-Waite + even Taylor deg-14 (err ~1e-6) ------
__device__ __forceinline__ ull pcos2(ull a) {
    ull km = fma2(a, dup2(0.15915494309189535f), dup2(12582912.0f));
    ull k  = add2(km, dup2(-12582912.0f));
    ull r  = fma2(k, dup2(-6.28318548202514648f), a);
    r      = fma2(k, dup2(1.74845553e-7f), r);      // r in [-pi, pi]
    ull t  = mul2(r, r);
    ull p  = fma2(dup2(-1.14707456e-11f), t, dup2(2.08767570e-9f));
    p = fma2(p, t, dup2(-2.75573192e-7f));
    p = fma2(p, t, dup2(2.48015873e-5f));
    p = fma2(p, t, dup2(-1.38888889e-3f));
    p = fma2(p, t, dup2(4.16666667e-2f));
    p = fma2(p, t, dup2(-0.5f));
    p = fma2(p, t, dup2(1.0f));
    return p;
}

// ---- kernel --------------------------------------------------------------
// 256 thr/block, 1 token/thread; lane stride 32B (4 lanes per 128B line).
//
// Shared record per f-pair fp (f = 2fp, 2fp+1), 16 ull = 128B:
//   [0..3] : (w1[2ep][fA], w1[2ep+1][fA])  ep=0..3   (GEMM1 row fA, e-packed)
//   [4..7] : same for fB
//   [8..15]: (w2[fA][e],  w2[fB][e])       e=0..7    (GEMM2 slice, f-packed)
// Seeds (b1[fA],0),(b1[fB],0) in a separate ulonglong2 array: 1 LDS.128/fp.
__global__ __launch_bounds__(256, 3)
void ffq_kernel(const float* __restrict__ x,
                const float* __restrict__ theta,
                const float* __restrict__ w1,
                const float* __restrict__ b1,
                const float* __restrict__ w2,
                const float* __restrict__ b2,
                float* __restrict__ out,
                int ntok) {
    __shared__ __align__(16) ull s_blk[16 * 16];
    __shared__ __align__(16) ull s_seed[F];     // [2fp]=(b1[fA],0) [2fp+1]=(b1[fB],0)
    __shared__ __align__(16) ull s_b2p[E];      // (b2[e], 0)
    __shared__ __align__(16) ull s_th[4];       // (theta[2i], theta[2i+1])

    const int tid = threadIdx.x;
    const int t = blockIdx.x * 256 + tid;       // token id

    // Kick off the x load first so LDG latency overlaps the smem prologue.
    const float4* x4 = reinterpret_cast<const float4*>(x);
    int ix = 2 * min(t, ntok - 1);
    float4 a0 = x4[ix], a1 = x4[ix + 1];

    if (tid < 256) {
        int i = tid;
        int fp = i >> 4, j = i & 15;
        int fA = 2 * fp, fB = fA + 1;
        ull v;
        if (j < 4) {
            int ep = j;
            v = pk2(w1[(2 * ep) * F + fA], w1[(2 * ep + 1) * F + fA]);
        } else if (j < 8) {
            int ep = j - 4;
            v = pk2(w1[(2 * ep) * F + fB], w1[(2 * ep + 1) * F + fB]);
        } else {
            int e = j - 8;
            v = pk2(w2[fA * E + e], w2[fB * E + e]);
        }
        s_blk[i] = v;
    }
    if (tid < F) s_seed[tid] = pk2(b1[tid], 0.0f);
    if (tid < E) s_b2p[tid] = pk2(b2[tid], 0.0f);
    if (tid < 4) s_th[tid] = pk2(theta[2 * tid], theta[2 * tid + 1]);
    __syncthreads();

    // q[ep] = cos(x[2ep..2ep+1] + theta[2ep..2ep+1]), packed over e.
    ull q0 = pcos2(add2(pk2(a0.x, a0.y), s_th[0]));
    ull q1 = pcos2(add2(pk2(a0.z, a0.w), s_th[1]));
    ull q2 = pcos2(add2(pk2(a1.x, a1.y), s_th[2]));
    ull q3 = pcos2(add2(pk2(a1.z, a1.w), s_th[3]));

    // o[e]: f-packed partial sums, seeded (b2[e], 0).
    ull o[E];
#pragma unroll
    for (int e = 0; e < E; ++e) o[e] = s_b2p[e];

#pragma unroll
    for (int fp = 0; fp < 16; ++fp) {
        const ulonglong2* rec = reinterpret_cast<const ulonglong2*>(&s_blk[fp * 16]);
        ulonglong2 wa0 = rec[0], wa1 = rec[1];   // GEMM1 row fA (4 e-pairs)
        ulonglong2 wb0 = rec[2], wb1 = rec[3];   // GEMM1 row fB
        ulonglong2 w20 = rec[4], w21 = rec[5], w22 = rec[6], w23 = rec[7];
        ulonglong2 sd  = reinterpret_cast<const ulonglong2*>(s_seed)[fp];

        // GEMM1: two 4-deep chains, seeded with (b1, 0).
        ull cA = fma2(q0, wa0.x, sd.x);
        cA = fma2(q1, wa0.y, cA);
        cA = fma2(q2, wa1.x, cA);
        cA = fma2(q3, wa1.y, cA);
        ull cB = fma2(q0, wb0.x, sd.y);
        cB = fma2(q1, wb0.y, cB);
        cB = fma2(q2, wb1.x, cB);
        cB = fma2(q3, wb1.y, cB);
        // horizontal add (register-pair halves are free) + ReLU.
        float lA, hAv, lB, hBv;
        up2(cA, lA, hAv);
        up2(cB, lB, hBv);
        float hA = fmaxf(lA + hAv, 0.0f);
        float hB = fmaxf(lB + hBv, 0.0f);
        ull h2 = pk2(hA, hB);
        // GEMM2: 8 independent f-packed accumulations.
        o[0] = fma2(h2, w20.x, o[0]);
        o[1] = fma2(h2, w20.y, o[1]);
        o[2] = fma2(h2, w21.x, o[2]);
        o[3] = fma2(h2, w21.y, o[3]);
        o[4] = fma2(h2, w22.x, o[4]);
        o[5] = fma2(h2, w22.y, o[5]);
        o[6] = fma2(h2, w23.x, o[6]);
        o[7] = fma2(h2, w23.y, o[7]);
    }

    float r[E];
#pragma unroll
    for (int e = 0; e < E; ++e) {
        float lo, hi;
        up2(o[e], lo, hi);
        r[e] = lo + hi;                         // absorbs b2 seed
    }
    if (t < ntok) {
        float4* o4 = reinterpret_cast<float4*>(out);
        o4[t * 2 + 0] = make_float4(r[0], r[1], r[2], r[3]);
        o4[t * 2 + 1] = make_float4(r[4], r[5], r[6], r[7]);
    }
}

extern "C" void kernel_launch(void* const* d_in, const int* in_sizes, int n_in,
                              void* d_out, int out_size) {
    const float* x     = (const float*)d_in[0];
    const float* theta = (const float*)d_in[1];
    const float* w1    = (const float*)d_in[2];
    const float* b1    = (const float*)d_in[3];
    const float* w2    = (const float*)d_in[4];
    const float* b2    = (const float*)d_in[5];
    float* out = (float*)d_out;

    int ntok = out_size / E;                    // B*S (output is [ntok, E])
    if (ntok <= 0) ntok = in_sizes[0] / E;
    int grid = (ntok + 255) / 256;              // 256 tokens per block
    ffq_kernel<<<grid, 256>>>(x, theta, w1, b1, w2, b2, out, ntok);
}

// round 9
// speedup vs baseline: 1.3243x; 1.3243x over previous
#include <cuda_runtime.h>

// FeedForwardQuantum: out = relu(cos(x+theta) @ W1 + b1) @ W2 + b2
// ntok = B*S = 524288, E = 8, F = 32.
// R9 == R8 resubmitted (R8 run died to container infra, no signal):
// 4 tokens/thread (LDS/token 72 -> 36; R7 A/B proved shared pipe binds when
// un-amortized) + e-packed GEMM2 accumulators (o: 16 -> 8 regs/token, no
// final horizontal add; b2 seeds directly). Natural regs ~115 under the
// launch_bounds(128,4) 128-reg cap -> no spills.

using ull = unsigned long long;

static constexpr int E = 8;
static constexpr int F = 32;

// ---- packed f32x2 helpers ------------------------------------------------
__device__ __forceinline__ ull pk2(float lo, float hi) {
    ull r; asm("mov.b64 %0, {%1,%2};" : "=l"(r) : "f"(lo), "f"(hi)); return r;
}
__device__ __forceinline__ void up2(ull v, float& lo, float& hi) {
    asm("mov.b64 {%0,%1}, %2;" : "=f"(lo), "=f"(hi) : "l"(v));
}
__device__ __forceinline__ ull dup2(float f) {
    ull r; asm("mov.b64 %0, {%1,%1};" : "=l"(r) : "f"(f)); return r;
}
__device__ __forceinline__ ull fma2(ull a, ull b, ull c) {
    ull r; asm("fma.rn.f32x2 %0, %1, %2, %3;" : "=l"(r) : "l"(a), "l"(b), "l"(c)); return r;
}
__device__ __forceinline__ ull add2(ull a, ull b) {
    ull r; asm("add.rn.f32x2 %0, %1, %2;" : "=l"(r) : "l"(a), "l"(b)); return r;
}
__device__ __forceinline__ ull mul2(ull a, ull b) {
    ull r; asm("mul.rn.f32x2 %0, %1, %2;" : "=l"(r) : "l"(a), "l"(b)); return r;
}

// ---- packed cosine: 2pi Cody-Waite + even Taylor deg-14 (err ~1e-6) ------
__device__ __forceinline__ ull pcos2(ull a) {
    ull km = fma2(a, dup2(0.15915494309189535f), dup2(12582912.0f));
    ull k  = add2(km, dup2(-12582912.0f));
    ull r  = fma2(k, dup2(-6.28318548202514648f), a);
    r      = fma2(k, dup2(1.74845553e-7f), r);      // r in [-pi, pi]
    ull t  = mul2(r, r);
    ull p  = fma2(dup2(-1.14707456e-11f), t, dup2(2.08767570e-9f));
    p = fma2(p, t, dup2(-2.75573192e-7f));
    p = fma2(p, t, dup2(2.48015873e-5f));
    p = fma2(p, t, dup2(-1.38888889e-3f));
    p = fma2(p, t, dup2(4.16666667e-2f));
    p = fma2(p, t, dup2(-0.5f));
    p = fma2(p, t, dup2(1.0f));
    return p;
}

// ---- kernel --------------------------------------------------------------
// 128 thr/block, 4 tokens/thread: warp covers 128 consecutive tokens,
// lane l takes tokens wbase+l+{0,32,64,96} (lane stride 32B: 4 lanes/line).
//
// Shared record per f-pair fp (f = 2fp, 2fp+1), 16 ull = 128B:
//   [ 0.. 3]: (w1[2ep][fA], w1[2ep+1][fA]) ep=0..3   (GEMM1 row fA, e-packed)
//   [ 4.. 7]: same for fB
//   [ 8..11]: (w2[fA][2ep], w2[fA][2ep+1]) ep=0..3   (GEMM2 row fA, e-packed)
//   [12..15]: same for fB
// Seeds (b1[fA],0),(b1[fB],0) separately: 9 LDS.128 per fp, serving 4 tokens.
__global__ __launch_bounds__(128, 4)
void ffq_kernel(const float* __restrict__ x,
                const float* __restrict__ theta,
                const float* __restrict__ w1,
                const float* __restrict__ b1,
                const float* __restrict__ w2,
                const float* __restrict__ b2,
                float* __restrict__ out,
                int ntok) {
    __shared__ __align__(16) ull s_blk[16 * 16];
    __shared__ __align__(16) ull s_seed[F];     // [2fp]=(b1[fA],0) [2fp+1]=(b1[fB],0)
    __shared__ __align__(16) ull s_b2e[4];      // (b2[2ep], b2[2ep+1])
    __shared__ __align__(16) ull s_th[4];       // (theta[2i], theta[2i+1])

    const int tid  = threadIdx.x;
    const int lane = tid & 31;
    const int warp = tid >> 5;
    const int wbase = blockIdx.x * 512 + warp * 128;
    const int t0 = wbase + lane;               // tokens t0+{0,32,64,96}

    // Kick off all 8 x-loads first: LDG latency overlaps the smem prologue.
    const float4* x4 = reinterpret_cast<const float4*>(x);
    float4 a[4][2];
#pragma unroll
    for (int j = 0; j < 4; ++j) {
        int ix = 2 * min(t0 + 32 * j, ntok - 1);
        a[j][0] = x4[ix];
        a[j][1] = x4[ix + 1];
    }

    for (int i = tid; i < 256; i += 128) {
        int fp = i >> 4, j = i & 15;
        int fA = 2 * fp, fB = fA + 1;
        ull v;
        if (j < 4) {
            int ep = j;
            v = pk2(w1[(2 * ep) * F + fA], w1[(2 * ep + 1) * F + fA]);
        } else if (j < 8) {
            int ep = j - 4;
            v = pk2(w1[(2 * ep) * F + fB], w1[(2 * ep + 1) * F + fB]);
        } else if (j < 12) {
            int ep = j - 8;
            v = pk2(w2[fA * E + 2 * ep], w2[fA * E + 2 * ep + 1]);
        } else {
            int ep = j - 12;
            v = pk2(w2[fB * E + 2 * ep], w2[fB * E + 2 * ep + 1]);
        }
        s_blk[i] = v;
    }
    if (tid < F) s_seed[tid] = pk2(b1[tid], 0.0f);
    if (tid < 4) s_b2e[tid] = pk2(b2[2 * tid], b2[2 * tid + 1]);
    if (tid < 4) s_th[tid] = pk2(theta[2 * tid], theta[2 * tid + 1]);
    __syncthreads();

    ull th0 = s_th[0], th1 = s_th[1], th2 = s_th[2], th3 = s_th[3];

    // q[tk][ep] = cos(x[2ep..2ep+1] + theta), e-packed. 8 regs/token.
    ull q[4][4];
#pragma unroll
    for (int tk = 0; tk < 4; ++tk) {
        q[tk][0] = pcos2(add2(pk2(a[tk][0].x, a[tk][0].y), th0));
        q[tk][1] = pcos2(add2(pk2(a[tk][0].z, a[tk][0].w), th1));
        q[tk][2] = pcos2(add2(pk2(a[tk][1].x, a[tk][1].y), th2));
        q[tk][3] = pcos2(add2(pk2(a[tk][1].z, a[tk][1].w), th3));
    }

    // o[tk][ep] = (out[2ep], out[2ep+1]) partials, seeded with b2. 8 regs/token.
    ull o[4][4];
#pragma unroll
    for (int tk = 0; tk < 4; ++tk)
#pragma unroll
        for (int ep = 0; ep < 4; ++ep) o[tk][ep] = s_b2e[ep];

#pragma unroll
    for (int fp = 0; fp < 16; ++fp) {
        const ulonglong2* rec = reinterpret_cast<const ulonglong2*>(&s_blk[fp * 16]);
        ulonglong2 wa0 = rec[0], wa1 = rec[1];   // GEMM1 fA
        ulonglong2 wb0 = rec[2], wb1 = rec[3];   // GEMM1 fB
        ulonglong2 va0 = rec[4], va1 = rec[5];   // GEMM2 fA (e-packed)
        ulonglong2 vb0 = rec[6], vb1 = rec[7];   // GEMM2 fB (e-packed)
        ulonglong2 sd  = reinterpret_cast<const ulonglong2*>(s_seed)[fp];
#pragma unroll
        for (int tk = 0; tk < 4; ++tk) {
            // GEMM1: two 4-deep e-packed chains seeded (b1, 0).
            ull cA = fma2(q[tk][0], wa0.x, sd.x);
            cA = fma2(q[tk][1], wa0.y, cA);
            cA = fma2(q[tk][2], wa1.x, cA);
            cA = fma2(q[tk][3], wa1.y, cA);
            ull cB = fma2(q[tk][0], wb0.x, sd.y);
            cB = fma2(q[tk][1], wb0.y, cB);
            cB = fma2(q[tk][2], wb1.x, cB);
            cB = fma2(q[tk][3], wb1.y, cB);
            float lA, hAv, lB, hBv;
            up2(cA, lA, hAv);
            up2(cB, lB, hBv);
            ull h2A = dup2(fmaxf(lA + hAv, 0.0f));   // relu(h[fA]) in both halves
            ull h2B = dup2(fmaxf(lB + hBv, 0.0f));
            // GEMM2: e-packed accumulate, 2 f's per ep.
            o[tk][0] = fma2(h2A, va0.x, o[tk][0]);
            o[tk][0] = fma2(h2B, vb0.x, o[tk][0]);
            o[tk][1] = fma2(h2A, va0.y, o[tk][1]);
            o[tk][1] = fma2(h2B, vb0.y, o[tk][1]);
            o[tk][2] = fma2(h2A, va1.x, o[tk][2]);
            o[tk][2] = fma2(h2B, vb1.x, o[tk][2]);
            o[tk][3] = fma2(h2A, va1.y, o[tk][3]);
            o[tk][3] = fma2(h2B, vb1.y, o[tk][3]);
        }
    }

    float4* o4 = reinterpret_cast<float4*>(out);
#pragma unroll
    for (int tk = 0; tk < 4; ++tk) {
        int t = t0 + 32 * tk;
        if (t < ntok) {
            float r0, r1, r2, r3, r4, r5, r6, r7;
            up2(o[tk][0], r0, r1);
            up2(o[tk][1], r2, r3);
            up2(o[tk][2], r4, r5);
            up2(o[tk][3], r6, r7);
            o4[t * 2 + 0] = make_float4(r0, r1, r2, r3);
            o4[t * 2 + 1] = make_float4(r4, r5, r6, r7);
        }
    }
}

extern "C" void kernel_launch(void* const* d_in, const int* in_sizes, int n_in,
                              void* d_out, int out_size) {
    const float* x     = (const float*)d_in[0];
    const float* theta = (const float*)d_in[1];
    const float* w1    = (const float*)d_in[2];
    const float* b1    = (const float*)d_in[3];
    const float* w2    = (const float*)d_in[4];
    const float* b2    = (const float*)d_in[5];
    float* out = (float*)d_out;

    int ntok = out_size / E;                    // B*S (output is [ntok, E])
    if (ntok <= 0) ntok = in_sizes[0] / E;
    int grid = (ntok + 511) / 512;              // 512 tokens per block
    ffq_kernel<<<grid, 128>>>(x, theta, w1, b1, w2, b2, out, ntok);
}